// round 1
// baseline (speedup 1.0000x reference)
#include <cuda_runtime.h>
#include <stdint.h>

#define NP     65536
#define NA     1024
#define NMAX   512
#define GRID   100
#define CELLS  (GRID * GRID)

// Scratch (allocation-free rule: __device__ globals)
__device__ int            g_cellCount[CELLS];
__device__ int            g_cellStart[CELLS + 1];
__device__ int            g_cursor[CELLS];
__device__ unsigned short g_binned[NP];   // point index 0..65535 fits u16 exactly

static __device__ __forceinline__ int cell_of(float x, float y) {
    int gx = (int)floorf(x);          // cell size = 1.0 (100/GRID)
    int gy = (int)floorf(y);
    gx = min(GRID - 1, max(0, gx));
    gy = min(GRID - 1, max(0, gy));
    return gy * GRID + gx;
}

__global__ void k_zero() {
    int i = blockIdx.x * blockDim.x + threadIdx.x;
    if (i < CELLS) g_cellCount[i] = 0;
}

__global__ void k_count(const float* __restrict__ pts) {
    int p = blockIdx.x * blockDim.x + threadIdx.x;
    if (p < NP) {
        float x = pts[p * 3 + 0], y = pts[p * 3 + 1];
        atomicAdd(&g_cellCount[cell_of(x, y)], 1);
    }
}

// Single-block exclusive scan of 10000 cell counts (1024 threads x 10 cells)
__global__ void k_scan() {
    __shared__ int wsum[32];
    int t = threadIdx.x;
    int base = t * 10;
    int loc[10];
    int s = 0;
#pragma unroll
    for (int i = 0; i < 10; i++) {
        int idx = base + i;
        int v = (idx < CELLS) ? g_cellCount[idx] : 0;
        loc[i] = s;
        s += v;
    }
    int lane = t & 31, wid = t >> 5;
    int v = s;
#pragma unroll
    for (int o = 1; o < 32; o <<= 1) {
        int u = __shfl_up_sync(0xFFFFFFFFu, v, o);
        if (lane >= o) v += u;
    }
    if (lane == 31) wsum[wid] = v;
    __syncthreads();
    if (wid == 0) {
        int w = wsum[lane];
#pragma unroll
        for (int o = 1; o < 32; o <<= 1) {
            int u = __shfl_up_sync(0xFFFFFFFFu, w, o);
            if (lane >= o) w += u;
        }
        wsum[lane] = w;
    }
    __syncthreads();
    int ex = v - s + (wid > 0 ? wsum[wid - 1] : 0);  // exclusive prefix for this thread
#pragma unroll
    for (int i = 0; i < 10; i++) {
        int idx = base + i;
        if (idx < CELLS) {
            int st = ex + loc[i];
            g_cellStart[idx] = st;
            g_cursor[idx]    = st;
        }
    }
    if (t == 1023) g_cellStart[CELLS] = ex + s;  // == NP
}

__global__ void k_scatter(const float* __restrict__ pts) {
    int p = blockIdx.x * blockDim.x + threadIdx.x;
    if (p < NP) {
        float x = pts[p * 3 + 0], y = pts[p * 3 + 1];
        int pos = atomicAdd(&g_cursor[cell_of(x, y)], 1);
        g_binned[pos] = (unsigned short)p;
    }
}

// One block per anchor: gather candidates from overlapping cells, test, sort, emit.
__global__ void __launch_bounds__(128, 8) k_anchor(
    const float* __restrict__ pts,
    const float* __restrict__ anch,
    float* __restrict__ out,
    float* __restrict__ counts_out)
{
    int a = blockIdx.x;
    int tid = threadIdx.x;

    float cx = anch[a * 6 + 0];
    float cy = anch[a * 6 + 1];
    float w  = anch[a * 6 + 3];
    float l  = anch[a * 6 + 4];
    float h  = anch[a * 6 + 5];
    float hw = w * 0.5f, hl = l * 0.5f;
    float x0 = cx - hw, x1 = cx + hw;
    float y0 = cy - hl, y1 = cy + hl;

    int gx0 = max(0, (int)floorf(x0));
    int gx1 = min(GRID - 1, (int)floorf(x1));
    int gy0 = max(0, (int)floorf(y0));
    int gy1 = min(GRID - 1, (int)floorf(y1));
    int ncx = gx1 - gx0 + 1;
    int ncy = gy1 - gy0 + 1;
    int ncells = ncx * ncy;   // <= 6*6 = 36 given w,l <= 5, cell = 1.0

    __shared__ int      s_cstart[64];
    __shared__ int      s_ccnt[64];
    __shared__ int      s_coff[65];
    __shared__ unsigned s_idx[NMAX];
    __shared__ int      s_count;

    if (tid == 0) s_count = 0;
    if (tid < ncells) {
        int cgx = gx0 + (tid % ncx);
        int cgy = gy0 + (tid / ncx);
        int c = cgy * GRID + cgx;
        int st = g_cellStart[c];
        s_cstart[tid] = st;
        s_ccnt[tid]   = g_cellStart[c + 1] - st;
    }
    __syncthreads();
    if (tid == 0) {
        int acc = 0;
        for (int j = 0; j < ncells; j++) { s_coff[j] = acc; acc += s_ccnt[j]; }
        s_coff[ncells] = acc;
    }
    __syncthreads();

    int total = s_coff[ncells];

    // Test candidates; compact hit indices (unordered) into shared.
    for (int i = tid; i < total; i += 128) {
        int j = 0;
        while (s_coff[j + 1] <= i) j++;
        int p = (int)g_binned[s_cstart[j] + (i - s_coff[j])];
        float px = pts[p * 3 + 0];
        float py = pts[p * 3 + 1];
        float pz = pts[p * 3 + 2];
        if (px >= x0 && px <= x1 && py >= y0 && py <= y1 && pz >= 0.0f && pz <= h) {
            int pos = atomicAdd(&s_count, 1);
            if (pos < NMAX) s_idx[pos] = (unsigned)p;
        }
    }
    __syncthreads();

    int cnt = s_count;
    int m = min(cnt, NMAX);

    // Bitonic sort ascending over next-pow2(m), sentinel-padded.
    int n = 1;
    while (n < m) n <<= 1;
    for (int i = m + tid; i < n; i += 128) s_idx[i] = 0xFFFFFFFFu;
    __syncthreads();
    for (int k = 2; k <= n; k <<= 1) {
        for (int j = k >> 1; j > 0; j >>= 1) {
            for (int i = tid; i < n; i += 128) {
                int l2 = i ^ j;
                if (l2 > i) {
                    unsigned va = s_idx[i], vb = s_idx[l2];
                    bool up = ((i & k) == 0);
                    if ((va > vb) == up) { s_idx[i] = vb; s_idx[l2] = va; }
                }
            }
            __syncthreads();
        }
    }

    // Emit: 512 slots, zero-padded; counts as float (exact for int < 2^24).
    float* outa = out + (size_t)a * NMAX * 3;
    for (int s = tid; s < NMAX; s += 128) {
        float ox = 0.0f, oy = 0.0f, oz = 0.0f;
        if (s < m) {
            int p = (int)s_idx[s];
            ox = pts[p * 3 + 0] - cx;
            oy = pts[p * 3 + 1] - cy;
            oz = pts[p * 3 + 2];
        }
        outa[s * 3 + 0] = ox;
        outa[s * 3 + 1] = oy;
        outa[s * 3 + 2] = oz;
    }
    if (tid == 0) counts_out[a] = (float)cnt;
}

extern "C" void kernel_launch(void* const* d_in, const int* in_sizes, int n_in,
                              void* d_out, int out_size) {
    const float* pts  = (const float*)d_in[0];   // (65536, 3) f32
    const float* anch = (const float*)d_in[1];   // (1024, 6)  f32
    float* out = (float*)d_out;                  // 1024*512*3 f32, then 1024 counts
    float* counts_out = out + (size_t)NA * NMAX * 3;

    k_zero<<<(CELLS + 255) / 256, 256>>>();
    k_count<<<(NP + 255) / 256, 256>>>(pts);
    k_scan<<<1, 1024>>>();
    k_scatter<<<(NP + 255) / 256, 256>>>(pts);
    k_anchor<<<NA, 128>>>(pts, anch, out, counts_out);
}

// round 3
// speedup vs baseline: 1.5682x; 1.5682x over previous
#include <cuda_runtime.h>
#include <stdint.h>

#define NP     65536
#define NA     1024
#define NMAX   512
#define GRID   100
#define CELLS  (GRID * GRID)
#define CAP    48          // max pts/cell; lambda=6.55 => P(>48) < 1e-20

// Scratch (allocation-free rule: __device__ globals)
__device__ int            g_cnt[CELLS];
__device__ unsigned short g_slot[CELLS * CAP];   // point index fits u16 exactly

static __device__ __forceinline__ int cell_of(float x, float y) {
    int gx = (int)floorf(x);          // cell size = 1.0
    int gy = (int)floorf(y);
    gx = min(GRID - 1, max(0, gx));
    gy = min(GRID - 1, max(0, gy));
    return gy * GRID + gx;
}

__global__ void k_zero() {
    int i = blockIdx.x * blockDim.x + threadIdx.x;
    if (i < CELLS) g_cnt[i] = 0;
}

static __device__ __forceinline__ void bin_one(float x, float y, int p) {
    int c = cell_of(x, y);
    int pos = atomicAdd(&g_cnt[c], 1);
    if (pos < CAP) g_slot[c * CAP + pos] = (unsigned short)p;
}

// 4 points per thread via 3 coalesced float4 loads. 16384 threads.
__global__ void k_bin(const float4* __restrict__ pts4) {
    int t = blockIdx.x * blockDim.x + threadIdx.x;   // 0..16383
    float4 a = pts4[t * 3 + 0];
    float4 b = pts4[t * 3 + 1];
    float4 c = pts4[t * 3 + 2];
    int p = 4 * t;
    bin_one(a.x, a.y, p + 0);
    bin_one(a.w, b.x, p + 1);
    bin_one(b.z, b.w, p + 2);
    bin_one(c.y, c.z, p + 3);
}

// One block per anchor.
__global__ void __launch_bounds__(128, 8) k_anchor(
    const float* __restrict__ pts,
    const float* __restrict__ anch,
    float* __restrict__ out,
    float* __restrict__ counts_out)
{
    int a = blockIdx.x;
    int tid = threadIdx.x;

    float cx = anch[a * 6 + 0];
    float cy = anch[a * 6 + 1];
    float w  = anch[a * 6 + 3];
    float l  = anch[a * 6 + 4];
    float h  = anch[a * 6 + 5];
    float hw = w * 0.5f, hl = l * 0.5f;
    float x0 = cx - hw, x1 = cx + hw;
    float y0 = cy - hl, y1 = cy + hl;

    int gx0 = max(0, (int)floorf(x0));
    int gx1 = min(GRID - 1, (int)floorf(x1));
    int gy0 = max(0, (int)floorf(y0));
    int gy1 = min(GRID - 1, (int)floorf(y1));
    int ncx = gx1 - gx0 + 1;
    int ncy = gy1 - gy0 + 1;
    int ncells = ncx * ncy;   // <= 36 (w,l <= 5, cell = 1.0)

    __shared__ int      s_base[40];           // slot base per cell
    __shared__ int      s_ccnt[40];
    __shared__ int      s_off[41];
    __shared__ unsigned s_key[NMAX];          // (pointIdx<<16) | slot
    __shared__ float    s_px[NMAX], s_py[NMAX], s_pz[NMAX];
    __shared__ __align__(16) float s_out[NMAX * 3];  // staged output (6KB), float4-aligned
    __shared__ int      s_count;

    if (tid == 0) s_count = 0;
    if (tid < ncells) {
        int cgx = gx0 + (tid % ncx);
        int cgy = gy0 + (tid / ncx);
        int c = cgy * GRID + cgx;
        s_base[tid] = c * CAP;
        s_ccnt[tid] = min(g_cnt[c], CAP);
    }
    // zero the staged output while we're at it
    for (int i = tid; i < NMAX * 3; i += 128) s_out[i] = 0.0f;
    __syncthreads();
    if (tid == 0) {
        int acc = 0;
        for (int j = 0; j < ncells; j++) { s_off[j] = acc; acc += s_ccnt[j]; }
        s_off[ncells] = acc;
    }
    __syncthreads();

    int total = s_off[ncells];

    // Test candidates; compact hits (unordered) with coords cached in shared.
    for (int i = tid; i < total; i += 128) {
        int j = 0;
        while (s_off[j + 1] <= i) j++;
        int p = (int)g_slot[s_base[j] + (i - s_off[j])];
        float px = pts[p * 3 + 0];
        float py = pts[p * 3 + 1];
        float pz = pts[p * 3 + 2];
        if (px >= x0 && px <= x1 && py >= y0 && py <= y1 && pz >= 0.0f && pz <= h) {
            int pos = atomicAdd(&s_count, 1);
            if (pos < NMAX) {
                s_key[pos] = ((unsigned)p << 16) | (unsigned)pos;
                s_px[pos] = px; s_py[pos] = py; s_pz[pos] = pz;
            }
        }
    }
    __syncthreads();

    int cnt = s_count;
    int m = min(cnt, NMAX);

    // Bitonic sort ascending on packed key => ascending point index (top_k order).
    int n = 1;
    while (n < m) n <<= 1;
    for (int i = m + tid; i < n; i += 128) s_key[i] = 0xFFFFFFFFu;
    __syncthreads();
    for (int k = 2; k <= n; k <<= 1) {
        for (int j = k >> 1; j > 0; j >>= 1) {
            for (int i = tid; i < n; i += 128) {
                int l2 = i ^ j;
                if (l2 > i) {
                    unsigned va = s_key[i], vb = s_key[l2];
                    bool up = ((i & k) == 0);
                    if ((va > vb) == up) { s_key[i] = vb; s_key[l2] = va; }
                }
            }
            __syncthreads();
        }
    }

    // Fill staged output from shared-cached coords.
    for (int s = tid; s < m; s += 128) {
        int pos = (int)(s_key[s] & 0xFFFFu);
        s_out[s * 3 + 0] = s_px[pos] - cx;
        s_out[s * 3 + 1] = s_py[pos] - cy;
        s_out[s * 3 + 2] = s_pz[pos];
    }
    __syncthreads();

    // Coalesced float4 flush: 1536 floats = 384 float4 per anchor.
    float4* outa = (float4*)(out + (size_t)a * NMAX * 3);
    const float4* so4 = (const float4*)s_out;
    for (int i = tid; i < NMAX * 3 / 4; i += 128) outa[i] = so4[i];
    if (tid == 0) counts_out[a] = (float)cnt;
}

extern "C" void kernel_launch(void* const* d_in, const int* in_sizes, int n_in,
                              void* d_out, int out_size) {
    const float* pts  = (const float*)d_in[0];   // (65536, 3) f32
    const float* anch = (const float*)d_in[1];   // (1024, 6)  f32
    float* out = (float*)d_out;                  // 1024*512*3 f32, then 1024 counts
    float* counts_out = out + (size_t)NA * NMAX * 3;

    k_zero<<<(CELLS + 255) / 256, 256>>>();
    k_bin<<<NP / 4 / 256, 256>>>((const float4*)pts);
    k_anchor<<<NA, 128>>>(pts, anch, out, counts_out);
}

// round 4
// speedup vs baseline: 1.6804x; 1.0715x over previous
#include <cuda_runtime.h>
#include <stdint.h>

#define NP     65536
#define NA     1024
#define NMAX   512
#define GRID   100
#define CELLS  (GRID * GRID)
#define CAP    48          // max pts/cell; lambda=6.55 => P(>48) < 1e-20

// Scratch (allocation-free rule: __device__ globals)
__device__ int            g_cnt[CELLS];
__device__ unsigned short g_slot[CELLS * CAP];   // point index 0..65535 fits u16

static __device__ __forceinline__ int cell_of(float x, float y) {
    int gx = (int)floorf(x);          // cell size = 1.0
    int gy = (int)floorf(y);
    gx = min(GRID - 1, max(0, gx));
    gy = min(GRID - 1, max(0, gy));
    return gy * GRID + gx;
}

// 1 point per thread: 65536 threads, 256 blocks. Only x,y needed.
__global__ void k_bin(const float* __restrict__ pts) {
    int p = blockIdx.x * blockDim.x + threadIdx.x;
    float x = __ldg(&pts[p * 3 + 0]);
    float y = __ldg(&pts[p * 3 + 1]);
    int c = cell_of(x, y);
    int pos = atomicAdd(&g_cnt[c], 1);
    if (pos < CAP) g_slot[c * CAP + pos] = (unsigned short)p;
}

// One block per anchor. 5 barriers total, no sort (rank-by-counting).
__global__ void __launch_bounds__(128, 8) k_anchor(
    const float* __restrict__ pts,
    const float* __restrict__ anch,
    float* __restrict__ out,
    float* __restrict__ counts_out)
{
    int a = blockIdx.x;
    int tid = threadIdx.x;

    float cx = anch[a * 6 + 0];
    float cy = anch[a * 6 + 1];
    float w  = anch[a * 6 + 3];
    float l  = anch[a * 6 + 4];
    float h  = anch[a * 6 + 5];
    float hw = w * 0.5f, hl = l * 0.5f;
    float x0 = cx - hw, x1 = cx + hw;
    float y0 = cy - hl, y1 = cy + hl;

    int gx0 = max(0, (int)floorf(x0));
    int gx1 = min(GRID - 1, (int)floorf(x1));
    int gy0 = max(0, (int)floorf(y0));
    int gy1 = min(GRID - 1, (int)floorf(y1));
    int ncx = gx1 - gx0 + 1;
    int ncy = gy1 - gy0 + 1;
    int ncells = ncx * ncy;   // <= 36 (w,l <= 5, cell = 1.0)

    __shared__ int           s_base[40];      // g_slot base per covered cell
    __shared__ int           s_ccnt[40];
    __shared__ int           s_off[40];       // exclusive offset per cell
    __shared__ int           s_total;
    __shared__ unsigned char s_cid[36 * CAP]; // candidate -> covered-cell id
    __shared__ unsigned      s_key[NMAX];     // point index of hit (compaction order)
    __shared__ float         s_px[NMAX], s_py[NMAX], s_pz[NMAX];
    __shared__ __align__(16) float s_out[NMAX * 3];  // staged output (6KB)
    __shared__ int           s_count;

    if (tid == 0) s_count = 0;
    if (tid < ncells) {
        int cgx = gx0 + (tid % ncx);
        int cgy = gy0 + (tid / ncx);
        int c = cgy * GRID + cgx;
        s_base[tid] = c * CAP;
        s_ccnt[tid] = min(g_cnt[c], CAP);
    }
    for (int i = tid; i < NMAX * 3; i += 128) s_out[i] = 0.0f;
    __syncthreads();                                   // (1)

    // Each covered cell computes its own exclusive offset (parallel, <=36 adds)
    // and fills the candidate->cell table.
    if (tid < ncells) {
        int off = 0;
        for (int j = 0; j < tid; j++) off += s_ccnt[j];
        s_off[tid] = off;
        int cnt = s_ccnt[tid];
        for (int k = 0; k < cnt; k++) s_cid[off + k] = (unsigned char)tid;
        if (tid == ncells - 1) s_total = off + cnt;
    }
    __syncthreads();                                   // (2)

    int total = s_total;

    // Test candidates; compact hits (unordered) with coords cached in shared.
    for (int i = tid; i < total; i += 128) {
        int j = (int)s_cid[i];
        int p = (int)g_slot[s_base[j] + (i - s_off[j])];
        float px = __ldg(&pts[p * 3 + 0]);
        float py = __ldg(&pts[p * 3 + 1]);
        float pz = __ldg(&pts[p * 3 + 2]);
        if (px >= x0 && px <= x1 && py >= y0 && py <= y1 && pz >= 0.0f && pz <= h) {
            int pos = atomicAdd(&s_count, 1);
            if (pos < NMAX) {
                s_key[pos] = (unsigned)p;
                s_px[pos] = px; s_py[pos] = py; s_pz[pos] = pz;
            }
        }
    }
    __syncthreads();                                   // (3)

    int cnt = s_count;
    int m = min(cnt, NMAX);

    // Rank-by-counting: rank = #keys smaller => ascending point-index order
    // (== jax.lax.top_k tie-break order). Barrier-free; inner LDS is broadcast.
    for (int s = tid; s < m; s += 128) {
        unsigned key = s_key[s];
        int r = 0;
        int j = 0;
        for (; j + 4 <= m; j += 4) {
            r += (s_key[j + 0] < key);
            r += (s_key[j + 1] < key);
            r += (s_key[j + 2] < key);
            r += (s_key[j + 3] < key);
        }
        for (; j < m; j++) r += (s_key[j] < key);
        s_out[r * 3 + 0] = s_px[s] - cx;
        s_out[r * 3 + 1] = s_py[s] - cy;
        s_out[r * 3 + 2] = s_pz[s];
    }
    __syncthreads();                                   // (4)

    // Coalesced float4 flush: 384 float4 per anchor.
    float4* outa = (float4*)(out + (size_t)a * NMAX * 3);
    const float4* so4 = (const float4*)s_out;
    for (int i = tid; i < NMAX * 3 / 4; i += 128) outa[i] = so4[i];
    if (tid == 0) counts_out[a] = (float)cnt;
}

extern "C" void kernel_launch(void* const* d_in, const int* in_sizes, int n_in,
                              void* d_out, int out_size) {
    const float* pts  = (const float*)d_in[0];   // (65536, 3) f32
    const float* anch = (const float*)d_in[1];   // (1024, 6)  f32
    float* out = (float*)d_out;                  // 1024*512*3 f32, then 1024 counts
    float* counts_out = out + (size_t)NA * NMAX * 3;

    // Zero the cell counters via a memset node (graph-capturable async op).
    void* cnt_ptr = nullptr;
    cudaGetSymbolAddress(&cnt_ptr, g_cnt);
    cudaMemsetAsync(cnt_ptr, 0, CELLS * sizeof(int));

    k_bin<<<NP / 256, 256>>>(pts);
    k_anchor<<<NA, 128>>>(pts, anch, out, counts_out);
}

// round 6
// speedup vs baseline: 2.3390x; 1.3919x over previous
#include <cuda_runtime.h>
#include <stdint.h>

#define NP     65536
#define NA     1024
#define NMAX   512
#define GRID   100
#define CELLS  (GRID * GRID)
#define CAP    48          // max pts/cell; lambda=6.55 => P(>48) < 1e-20

// Scratch (allocation-free rule: __device__ globals)
__device__ int    g_cnt[CELLS];
__device__ float4 g_bin[CELLS * CAP];   // packed (x, y, z, (float)pointIdx) — idx<=65535 exact in f32

static __device__ __forceinline__ int cell_of(float x, float y) {
    int gx = (int)floorf(x);          // cell size = 1.0
    int gy = (int)floorf(y);
    gx = min(GRID - 1, max(0, gx));
    gy = min(GRID - 1, max(0, gy));
    return gy * GRID + gx;
}

// 1 point per thread: 65536 threads. Packs full record into the bin.
__global__ void k_bin(const float* __restrict__ pts) {
    int p = blockIdx.x * blockDim.x + threadIdx.x;
    float x = __ldg(&pts[p * 3 + 0]);
    float y = __ldg(&pts[p * 3 + 1]);
    float z = __ldg(&pts[p * 3 + 2]);
    int c = cell_of(x, y);
    int pos = atomicAdd(&g_cnt[c], 1);
    if (pos < CAP) g_bin[c * CAP + pos] = make_float4(x, y, z, (float)p);
}

// One block per anchor. 4 barriers, no sort (rank-by-counting), no point gathers.
__global__ void __launch_bounds__(128, 8) k_anchor(
    const float* __restrict__ anch,
    float* __restrict__ out,
    float* __restrict__ counts_out)
{
    int a = blockIdx.x;
    int tid = threadIdx.x;

    float cx = anch[a * 6 + 0];
    float cy = anch[a * 6 + 1];
    float w  = anch[a * 6 + 3];
    float l  = anch[a * 6 + 4];
    float h  = anch[a * 6 + 5];
    float hw = w * 0.5f, hl = l * 0.5f;
    float x0 = cx - hw, x1 = cx + hw;
    float y0 = cy - hl, y1 = cy + hl;

    int gx0 = max(0, (int)floorf(x0));
    int gx1 = min(GRID - 1, (int)floorf(x1));
    int gy0 = max(0, (int)floorf(y0));
    int gy1 = min(GRID - 1, (int)floorf(y1));
    int ncx = gx1 - gx0 + 1;
    int ncy = gy1 - gy0 + 1;
    int ncells = ncx * ncy;   // <= 36 (w,l <= 5, cell = 1.0)

    __shared__ int           s_base[40];      // g_bin base per covered cell
    __shared__ int           s_ccnt[40];
    __shared__ int           s_off[40];       // exclusive offset per cell
    __shared__ int           s_total;
    __shared__ unsigned char s_cid[36 * CAP]; // candidate -> covered-cell id
    __shared__ float         s_key[NMAX];     // point index (as float, exact) in compaction order
    __shared__ float         s_px[NMAX], s_py[NMAX], s_pz[NMAX];
    __shared__ __align__(16) float s_out[NMAX * 3];  // staged output; only [0,3m) written
    __shared__ int           s_count;

    if (tid == 0) s_count = 0;
    if (tid < ncells) {
        int cgx = gx0 + (tid % ncx);
        int cgy = gy0 + (tid / ncx);
        int c = cgy * GRID + cgx;
        s_base[tid] = c * CAP;
        s_ccnt[tid] = min(g_cnt[c], CAP);
    }
    __syncthreads();                                   // (1)

    // Each covered cell computes its own exclusive offset and fills the
    // candidate->cell table.
    if (tid < ncells) {
        int off = 0;
        for (int j = 0; j < tid; j++) off += s_ccnt[j];
        s_off[tid] = off;
        int cnt = s_ccnt[tid];
        for (int k = 0; k < cnt; k++) s_cid[off + k] = (unsigned char)tid;
        if (tid == ncells - 1) s_total = off + cnt;
    }
    __syncthreads();                                   // (2)

    int total = s_total;

    // Test candidates; single LDG.128 per candidate (record packed in bin).
    for (int i = tid; i < total; i += 128) {
        int j = (int)s_cid[i];
        float4 r = __ldg(&g_bin[s_base[j] + (i - s_off[j])]);
        if (r.x >= x0 && r.x <= x1 && r.y >= y0 && r.y <= y1 &&
            r.z >= 0.0f && r.z <= h) {
            int pos = atomicAdd(&s_count, 1);
            if (pos < NMAX) {
                s_key[pos] = r.w;
                s_px[pos] = r.x; s_py[pos] = r.y; s_pz[pos] = r.z;
            }
        }
    }
    __syncthreads();                                   // (3)

    int cnt = s_count;
    int m = min(cnt, NMAX);

    // Rank-by-counting: rank = #keys smaller => ascending point-index order
    // (== jax.lax.top_k tie-break). Barrier-free; inner LDS is broadcast.
    for (int s = tid; s < m; s += 128) {
        float key = s_key[s];
        int r = 0;
        int j = 0;
        for (; j + 4 <= m; j += 4) {
            r += (s_key[j + 0] < key);
            r += (s_key[j + 1] < key);
            r += (s_key[j + 2] < key);
            r += (s_key[j + 3] < key);
        }
        for (; j < m; j++) r += (s_key[j] < key);
        s_out[r * 3 + 0] = s_px[s] - cx;
        s_out[r * 3 + 1] = s_py[s] - cy;
        s_out[r * 3 + 2] = s_pz[s];
    }
    __syncthreads();                                   // (4)

    // Coalesced float4 flush; pad slots >= m zeroed via predicate (no pre-zero).
    int limit = 3 * m;
    float4* outa = (float4*)(out + (size_t)a * NMAX * 3);
    const float4* so4 = (const float4*)s_out;
    for (int i = tid; i < NMAX * 3 / 4; i += 128) {
        float4 v = so4[i];           // may read garbage beyond limit; masked below
        int f = 4 * i;
        if (f + 0 >= limit) v.x = 0.0f;
        if (f + 1 >= limit) v.y = 0.0f;
        if (f + 2 >= limit) v.z = 0.0f;
        if (f + 3 >= limit) v.w = 0.0f;
        outa[i] = v;
    }
    if (tid == 0) counts_out[a] = (float)cnt;
}

extern "C" void kernel_launch(void* const* d_in, const int* in_sizes, int n_in,
                              void* d_out, int out_size) {
    const float* pts  = (const float*)d_in[0];   // (65536, 3) f32
    const float* anch = (const float*)d_in[1];   // (1024, 6)  f32
    float* out = (float*)d_out;                  // 1024*512*3 f32, then 1024 counts
    float* counts_out = out + (size_t)NA * NMAX * 3;

    // Zero the cell counters via a memset node (graph-capturable async op).
    void* cnt_ptr = nullptr;
    cudaGetSymbolAddress(&cnt_ptr, g_cnt);
    cudaMemsetAsync(cnt_ptr, 0, CELLS * sizeof(int));

    k_bin<<<NP / 256, 256>>>(pts);
    k_anchor<<<NA, 128>>>(anch, out, counts_out);
}

// round 7
// speedup vs baseline: 2.3793x; 1.0172x over previous
#include <cuda_runtime.h>
#include <stdint.h>

#define NP     65536
#define NA     1024
#define NMAX   512
#define GRID   100
#define CELLS  (GRID * GRID)
#define CAP    48          // max pts/cell; lambda=6.55 => P(>48) < 1e-20

// Scratch (allocation-free rule: __device__ globals)
__device__ int    g_cnt[CELLS];
__device__ float4 g_bin[CELLS * CAP];   // packed (x, y, z, (float)pointIdx); idx<=65535 exact in f32

static __device__ __forceinline__ int cell_of(float x, float y) {
    int gx = (int)floorf(x);          // cell size = 1.0
    int gy = (int)floorf(y);
    gx = min(GRID - 1, max(0, gx));
    gy = min(GRID - 1, max(0, gy));
    return gy * GRID + gx;
}

// 1 point per thread: 65536 threads. Packs full record into the bin.
__global__ void k_bin(const float* __restrict__ pts) {
    int p = blockIdx.x * blockDim.x + threadIdx.x;
    float x = __ldg(&pts[p * 3 + 0]);
    float y = __ldg(&pts[p * 3 + 1]);
    float z = __ldg(&pts[p * 3 + 2]);
    int c = cell_of(x, y);
    int pos = atomicAdd(&g_cnt[c], 1);
    if (pos < CAP) g_bin[c * CAP + pos] = make_float4(x, y, z, (float)p);
}

// One block per anchor. 3 barriers, ~4.3KB smem => whole grid in one wave.
__global__ void __launch_bounds__(128, 8) k_anchor(
    const float* __restrict__ pts,
    const float* __restrict__ anch,
    float* __restrict__ out,
    float* __restrict__ counts_out)
{
    int a = blockIdx.x;
    int tid = threadIdx.x;
    int lane = tid & 31;

    float cx = anch[a * 6 + 0];
    float cy = anch[a * 6 + 1];
    float w  = anch[a * 6 + 3];
    float l  = anch[a * 6 + 4];
    float h  = anch[a * 6 + 5];
    float hw = w * 0.5f, hl = l * 0.5f;
    float x0 = cx - hw, x1 = cx + hw;
    float y0 = cy - hl, y1 = cy + hl;

    int gx0 = max(0, (int)floorf(x0));
    int gx1 = min(GRID - 1, (int)floorf(x1));
    int gy0 = max(0, (int)floorf(y0));
    int gy1 = min(GRID - 1, (int)floorf(y1));
    int ncx = gx1 - gx0 + 1;
    int ncy = gy1 - gy0 + 1;
    int ncells = ncx * ncy;   // <= 36 (w,l <= 5, cell = 1.0)

    __shared__ int           s_base[40];      // g_bin base per covered cell
    __shared__ int           s_ccnt[40];
    __shared__ int           s_off[40];       // exclusive offset per cell
    __shared__ int           s_total;
    __shared__ unsigned char s_cid[36 * CAP]; // candidate -> covered-cell id
    __shared__ float         s_key[NMAX];     // point index as float (exact)
    __shared__ int           s_count;

    if (tid == 0) s_count = 0;
    if (tid < ncells) {
        int cgx = gx0 + (tid % ncx);
        int cgy = gy0 + (tid / ncx);
        int c = cgy * GRID + cgx;
        s_base[tid] = c * CAP;
        s_ccnt[tid] = min(g_cnt[c], CAP);
    }
    __syncthreads();                                   // (1)

    if (tid < ncells) {
        int off = 0;
        for (int j = 0; j < tid; j++) off += s_ccnt[j];
        s_off[tid] = off;
        int cnt = s_ccnt[tid];
        for (int k = 0; k < cnt; k++) s_cid[off + k] = (unsigned char)tid;
        if (tid == ncells - 1) s_total = off + cnt;
    }
    __syncthreads();                                   // (2)

    int total = s_total;

    // Phase A: test candidates, warp-aggregated key compaction (order-free).
    for (int i0 = 0; i0 < total; i0 += 128) {
        int i = i0 + tid;
        bool hit = false;
        float key = 0.0f;
        if (i < total) {
            int j = (int)s_cid[i];
            float4 r = __ldg(&g_bin[s_base[j] + (i - s_off[j])]);
            hit = (r.x >= x0 && r.x <= x1 && r.y >= y0 && r.y <= y1 &&
                   r.z >= 0.0f && r.z <= h);
            key = r.w;
        }
        unsigned bal = __ballot_sync(0xFFFFFFFFu, hit);
        int nb = __popc(bal);
        int base = 0;
        if (lane == 0 && nb) base = atomicAdd(&s_count, nb);
        base = __shfl_sync(0xFFFFFFFFu, base, 0);
        if (hit) {
            int pos = base + __popc(bal & ((1u << lane) - 1u));
            if (pos < NMAX) s_key[pos] = key;
        }
    }
    __syncthreads();                                   // (3)

    int cnt = s_count;
    int m = min(cnt, NMAX);
    float* outa = out + (size_t)a * NMAX * 3;

    // Phase B, step 1: threads s<m issue their coord gathers early (L2 hits).
    float mykey = 0.0f, px = 0.0f, py = 0.0f, pz = 0.0f;
    int s = tid;
    bool own = (s < m);
    if (own) {
        mykey = s_key[s];
        int p = (int)mykey;
        px = __ldg(&pts[p * 3 + 0]);
        py = __ldg(&pts[p * 3 + 1]);
        pz = __ldg(&pts[p * 3 + 2]);
    }

    // Step 2: ALL threads zero the tail while gathers are in flight.
    for (int f = 3 * m + tid; f < NMAX * 3; f += 128) outa[f] = 0.0f;

    // Step 3: rank-by-counting (broadcast LDS) + direct ranked store.
    if (own) {
        int r = 0;
        int j = 0;
        for (; j + 4 <= m; j += 4) {
            r += (s_key[j + 0] < mykey);
            r += (s_key[j + 1] < mykey);
            r += (s_key[j + 2] < mykey);
            r += (s_key[j + 3] < mykey);
        }
        for (; j < m; j++) r += (s_key[j] < mykey);
        outa[r * 3 + 0] = px - cx;
        outa[r * 3 + 1] = py - cy;
        outa[r * 3 + 2] = pz;
    }
    // Rare case m > 128: handle remaining ranks (same pattern, strided).
    for (s = tid + 128; s < m; s += 128) {
        float key = s_key[s];
        int p = (int)key;
        float qx = __ldg(&pts[p * 3 + 0]);
        float qy = __ldg(&pts[p * 3 + 1]);
        float qz = __ldg(&pts[p * 3 + 2]);
        int r = 0;
        for (int j = 0; j < m; j++) r += (s_key[j] < key);
        outa[r * 3 + 0] = qx - cx;
        outa[r * 3 + 1] = qy - cy;
        outa[r * 3 + 2] = qz;
    }
    if (tid == 0) counts_out[a] = (float)cnt;
}

extern "C" void kernel_launch(void* const* d_in, const int* in_sizes, int n_in,
                              void* d_out, int out_size) {
    const float* pts  = (const float*)d_in[0];   // (65536, 3) f32
    const float* anch = (const float*)d_in[1];   // (1024, 6)  f32
    float* out = (float*)d_out;                  // 1024*512*3 f32, then 1024 counts
    float* counts_out = out + (size_t)NA * NMAX * 3;

    // Zero the cell counters via a memset node (graph-capturable async op).
    void* cnt_ptr = nullptr;
    cudaGetSymbolAddress(&cnt_ptr, g_cnt);
    cudaMemsetAsync(cnt_ptr, 0, CELLS * sizeof(int));

    k_bin<<<NP / 256, 256>>>(pts);
    k_anchor<<<NA, 128>>>(pts, anch, out, counts_out);
}

// round 8
// speedup vs baseline: 2.3844x; 1.0022x over previous
#include <cuda_runtime.h>
#include <stdint.h>

#define NP     65536
#define NA     1024
#define NMAX   512
#define GRID   100
#define CELLS  (GRID * GRID)
#define CAP    48          // max pts/cell; lambda=6.55 => P(>48) < 1e-20
#define TPB    256         // threads per anchor block

// Scratch (allocation-free rule: __device__ globals)
__device__ int    g_cnt[CELLS];
__device__ float4 g_bin[CELLS * CAP];   // packed (x, y, z, (float)pointIdx); idx<=65535 exact in f32

static __device__ __forceinline__ int cell_of(float x, float y) {
    int gx = (int)floorf(x);          // cell size = 1.0
    int gy = (int)floorf(y);
    gx = min(GRID - 1, max(0, gx));
    gy = min(GRID - 1, max(0, gy));
    return gy * GRID + gx;
}

// 1 point per thread: 65536 threads. Packs full record into the bin.
__global__ void k_bin(const float* __restrict__ pts) {
    int p = blockIdx.x * blockDim.x + threadIdx.x;
    float x = __ldg(&pts[p * 3 + 0]);
    float y = __ldg(&pts[p * 3 + 1]);
    float z = __ldg(&pts[p * 3 + 2]);
    int c = cell_of(x, y);
    int pos = atomicAdd(&g_cnt[c], 1);
    if (pos < CAP) g_bin[c * CAP + pos] = make_float4(x, y, z, (float)p);
}

// One block per anchor, 256 threads: phase A in one strided pass, high occupancy.
__global__ void __launch_bounds__(TPB, 6) k_anchor(
    const float* __restrict__ pts,
    const float* __restrict__ anch,
    float* __restrict__ out,
    float* __restrict__ counts_out)
{
    int a = blockIdx.x;
    int tid = threadIdx.x;
    int lane = tid & 31;

    // Anchor row = 6 floats at byte offset a*24 (8-aligned): 3 broadcast LDG.64.
    const float2* arow = (const float2*)(anch + a * 6);
    float2 f01 = __ldg(&arow[0]);   // cx, cy
    float2 f23 = __ldg(&arow[1]);   // cz, w
    float2 f45 = __ldg(&arow[2]);   // l, h
    float cx = f01.x, cy = f01.y;
    float w = f23.y, l = f45.x, h = f45.y;
    float hw = w * 0.5f, hl = l * 0.5f;
    float x0 = cx - hw, x1 = cx + hw;
    float y0 = cy - hl, y1 = cy + hl;

    int gx0 = max(0, (int)floorf(x0));
    int gx1 = min(GRID - 1, (int)floorf(x1));
    int gy0 = max(0, (int)floorf(y0));
    int gy1 = min(GRID - 1, (int)floorf(y1));
    int ncx = gx1 - gx0 + 1;
    int ncy = gy1 - gy0 + 1;
    int ncells = ncx * ncy;   // <= 36 (w,l <= 5, cell = 1.0)

    __shared__ int           s_base[40];      // g_bin base per covered cell
    __shared__ int           s_ccnt[40];
    __shared__ int           s_off[40];       // exclusive offset per cell
    __shared__ int           s_total;
    __shared__ unsigned char s_cid[36 * CAP]; // candidate -> covered-cell id
    __shared__ float         s_key[NMAX];     // point index as float (exact)
    __shared__ int           s_count;

    if (tid == 0) s_count = 0;
    if (tid < ncells) {
        int cgx = gx0 + (tid % ncx);
        int cgy = gy0 + (tid / ncx);
        int c = cgy * GRID + cgx;
        s_base[tid] = c * CAP;
        s_ccnt[tid] = min(g_cnt[c], CAP);
    }
    __syncthreads();                                   // (1)

    if (tid < ncells) {
        int off = 0;
        for (int j = 0; j < tid; j++) off += s_ccnt[j];
        s_off[tid] = off;
        int cnt = s_ccnt[tid];
        for (int k = 0; k < cnt; k++) s_cid[off + k] = (unsigned char)tid;
        if (tid == ncells - 1) s_total = off + cnt;
    }
    __syncthreads();                                   // (2)

    int total = s_total;

    // Phase A: test candidates (usually ONE pass: total ~230 < 256 threads),
    // warp-aggregated key compaction (order-free).
    for (int i0 = 0; i0 < total; i0 += TPB) {
        int i = i0 + tid;
        bool hit = false;
        float key = 0.0f;
        if (i < total) {
            int j = (int)s_cid[i];
            float4 r = __ldg(&g_bin[s_base[j] + (i - s_off[j])]);
            hit = (r.x >= x0 && r.x <= x1 && r.y >= y0 && r.y <= y1 &&
                   r.z >= 0.0f && r.z <= h);
            key = r.w;
        }
        unsigned bal = __ballot_sync(0xFFFFFFFFu, hit);
        int nb = __popc(bal);
        int base = 0;
        if (lane == 0 && nb) base = atomicAdd(&s_count, nb);
        base = __shfl_sync(0xFFFFFFFFu, base, 0);
        if (hit) {
            int pos = base + __popc(bal & ((1u << lane) - 1u));
            if (pos < NMAX) s_key[pos] = key;
        }
    }
    __syncthreads();                                   // (3)

    int cnt = s_count;
    int m = min(cnt, NMAX);
    float* outa = out + (size_t)a * NMAX * 3;

    // Phase B, step 1: threads s<m issue their coord gathers early (L2 hits).
    float mykey = 0.0f, px = 0.0f, py = 0.0f, pz = 0.0f;
    bool own = (tid < m);
    if (own) {
        mykey = s_key[tid];
        int p = (int)mykey;
        px = __ldg(&pts[p * 3 + 0]);
        py = __ldg(&pts[p * 3 + 1]);
        pz = __ldg(&pts[p * 3 + 2]);
    }

    // Step 2: ALL threads zero the tail while gathers are in flight.
    for (int f = 3 * m + tid; f < NMAX * 3; f += TPB) outa[f] = 0.0f;

    // Step 3: rank-by-counting (broadcast LDS) + direct ranked store.
    if (own) {
        int r = 0;
        int j = 0;
        for (; j + 4 <= m; j += 4) {
            r += (s_key[j + 0] < mykey);
            r += (s_key[j + 1] < mykey);
            r += (s_key[j + 2] < mykey);
            r += (s_key[j + 3] < mykey);
        }
        for (; j < m; j++) r += (s_key[j] < mykey);
        outa[r * 3 + 0] = px - cx;
        outa[r * 3 + 1] = py - cy;
        outa[r * 3 + 2] = pz;
    }
    // Rare case m > TPB: handle remaining ranks (same pattern, strided).
    for (int s = tid + TPB; s < m; s += TPB) {
        float key = s_key[s];
        int p = (int)key;
        float qx = __ldg(&pts[p * 3 + 0]);
        float qy = __ldg(&pts[p * 3 + 1]);
        float qz = __ldg(&pts[p * 3 + 2]);
        int r = 0;
        for (int j = 0; j < m; j++) r += (s_key[j] < key);
        outa[r * 3 + 0] = qx - cx;
        outa[r * 3 + 1] = qy - cy;
        outa[r * 3 + 2] = qz;
    }
    if (tid == 0) counts_out[a] = (float)cnt;
}

extern "C" void kernel_launch(void* const* d_in, const int* in_sizes, int n_in,
                              void* d_out, int out_size) {
    const float* pts  = (const float*)d_in[0];   // (65536, 3) f32
    const float* anch = (const float*)d_in[1];   // (1024, 6)  f32
    float* out = (float*)d_out;                  // 1024*512*3 f32, then 1024 counts
    float* counts_out = out + (size_t)NA * NMAX * 3;

    // Zero the cell counters via a memset node (graph-capturable async op).
    void* cnt_ptr = nullptr;
    cudaGetSymbolAddress(&cnt_ptr, g_cnt);
    cudaMemsetAsync(cnt_ptr, 0, CELLS * sizeof(int));

    k_bin<<<NP / 256, 256>>>(pts);
    k_anchor<<<NA, TPB>>>(pts, anch, out, counts_out);
}